// round 8
// baseline (speedup 1.0000x reference)
#include <cuda_runtime.h>
#include <cstdint>

#define BQ 8
#define CQ 32
#define KQ 512
#define IT 4            // i-rows per block

// ---------------------------------------------------------------------------
// Threefry-2x32, key (0, 42); partitionable scheme: bits(idx) = o0 ^ o1 of
// threefry(key, (0, idx)).
// ---------------------------------------------------------------------------
__device__ __forceinline__ uint32_t rotl32(uint32_t x, int r) {
    return (x << r) | (x >> (32 - r));
}
__device__ __forceinline__ void threefry_0_42(uint32_t x0, uint32_t x1,
                                              uint32_t& o0, uint32_t& o1) {
    const uint32_t ks0 = 0u, ks1 = 42u, ks2 = 0u ^ 42u ^ 0x1BD11BDAu;
    x0 += ks0; x1 += ks1;
    x0 += x1; x1 = rotl32(x1, 13); x1 ^= x0;
    x0 += x1; x1 = rotl32(x1, 15); x1 ^= x0;
    x0 += x1; x1 = rotl32(x1, 26); x1 ^= x0;
    x0 += x1; x1 = rotl32(x1, 6);  x1 ^= x0;
    x0 += ks1; x1 += ks2 + 1u;
    x0 += x1; x1 = rotl32(x1, 17); x1 ^= x0;
    x0 += x1; x1 = rotl32(x1, 29); x1 ^= x0;
    x0 += x1; x1 = rotl32(x1, 16); x1 ^= x0;
    x0 += x1; x1 = rotl32(x1, 24); x1 ^= x0;
    x0 += ks2; x1 += ks0 + 2u;
    x0 += x1; x1 = rotl32(x1, 13); x1 ^= x0;
    x0 += x1; x1 = rotl32(x1, 15); x1 ^= x0;
    x0 += x1; x1 = rotl32(x1, 26); x1 ^= x0;
    x0 += x1; x1 = rotl32(x1, 6);  x1 ^= x0;
    x0 += ks0; x1 += ks1 + 3u;
    x0 += x1; x1 = rotl32(x1, 17); x1 ^= x0;
    x0 += x1; x1 = rotl32(x1, 29); x1 ^= x0;
    x0 += x1; x1 = rotl32(x1, 16); x1 ^= x0;
    x0 += x1; x1 = rotl32(x1, 24); x1 ^= x0;
    x0 += ks1; x1 += ks2 + 4u;
    x0 += x1; x1 = rotl32(x1, 13); x1 ^= x0;
    x0 += x1; x1 = rotl32(x1, 15); x1 ^= x0;
    x0 += x1; x1 = rotl32(x1, 26); x1 ^= x0;
    x0 += x1; x1 = rotl32(x1, 6);  x1 ^= x0;
    x0 += ks2; x1 += ks0 + 5u;
    o0 = x0; o1 = x1;
}
__device__ __forceinline__ uint32_t jax_bits_partitionable(uint32_t idx) {
    uint32_t o0, o1;
    threefry_0_42(0u, idx, o0, o1);
    return o0 ^ o1;
}
__device__ __forceinline__ float gumbel_from_bits(uint32_t bits) {
    float f = __uint_as_float((bits >> 9) | 0x3F800000u) - 1.0f;
    float u = fmaxf(__fadd_rn(f, 1e-10f), 1e-10f);
    return -logf(-logf(u));
}

// add-class ops as FFMA intrinsics (bit-exact: +-1.0 product exact, single rn)
__device__ __forceinline__ float fsub_via_fma(float a, float b) {
    return __fmaf_rn(b, -1.0f, a);
}
__device__ __forceinline__ float fadd_via_fma(float a, float b) {
    return __fmaf_rn(a, 1.0f, b);
}

// ---------------------------------------------------------------------------
// Kernel 0: zero the output (atomic accumulation target).
// ---------------------------------------------------------------------------
__global__ void __launch_bounds__(512)
k_init(float* __restrict__ out) {
    out[blockIdx.x * 512u + threadIdx.x] = 0.0f;
}

// ---------------------------------------------------------------------------
// Fused kernel: dist -> rowmax -> logit -> gumbel decision -> atomic 1/8 adds.
// grid (KQ/IT, BQ) = (128, 8), 512 threads (thread = j).
// ---------------------------------------------------------------------------
__global__ void __launch_bounds__(KQ)
k_fused(const float* __restrict__ amp, const float* __restrict__ ph,
        const float* __restrict__ A,
        const float* __restrict__ wa_p, const float* __restrict__ wp_p,
        float* __restrict__ out) {
    const int b  = blockIdx.y;
    const int i0 = blockIdx.x * IT;
    const int j  = threadIdx.x;

    __shared__ float s_ai[CQ][IT];
    __shared__ float s_pi[CQ][IT];
    __shared__ float s_max[IT][16];

    const float wa = wa_p[0];
    const float wp = wp_p[0];
    // wa = wp = 0.5 fast path is bit-exact: rn(0.5*x) exact (pow-2 scale), so
    // f = rn(0.5*ad + 0.5*pd) = 0.5*rn(ad+pd) and rn(f*Ajj) = rn(s*(0.5*Ajj)).
    const bool half = (__float_as_uint(wa) == 0x3F000000u) &&
                      (__float_as_uint(wp) == 0x3F000000u);

    if (threadIdx.x < IT * CQ) {
        int t = threadIdx.x % IT;
        int c = threadIdx.x / IT;
        s_ai[c][t] = amp[(b * CQ + c) * KQ + i0 + t];
        s_pi[c][t] = ph [(b * CQ + c) * KQ + i0 + t];
    }
    __syncthreads();

    const float Ajj = A[j * KQ + j];
    const float Aj2 = __fmul_rn(0.5f, Ajj);   // exact

    float acc[IT];
#pragma unroll
    for (int t = 0; t < IT; t++) acc[t] = 0.0f;

    const float* ap = amp + (size_t)b * CQ * KQ + j;
    const float* pp = ph  + (size_t)b * CQ * KQ + j;

    if (half) {
#pragma unroll 8
        for (int c = 0; c < CQ; c++) {
            float aj = ap[c * KQ];
            float pj = pp[c * KQ];
#pragma unroll
            for (int t = 0; t < IT; t++) {
                float ad = fsub_via_fma(s_ai[c][t], aj);   // rn(ai - aj)
                float pd = fsub_via_fma(s_pi[c][t], pj);   // rn(pi - pj)
                float s  = fadd_via_fma(ad, pd);           // = 2*f bit-exactly
                float tt = __fmul_rn(s, Aj2);              // = rn(f*Ajj)
                float sq = __fmul_rn(tt, tt);
                acc[t]   = fadd_via_fma(sq, acc[t]);
            }
        }
    } else {
#pragma unroll 8
        for (int c = 0; c < CQ; c++) {
            float aj = ap[c * KQ];
            float pj = pp[c * KQ];
#pragma unroll
            for (int t = 0; t < IT; t++) {
                float ad = fsub_via_fma(s_ai[c][t], aj);
                float pd = fsub_via_fma(s_pi[c][t], pj);
                float f  = fadd_via_fma(__fmul_rn(wa, ad), __fmul_rn(wp, pd));
                float tt = __fmul_rn(f, Ajj);
                float sq = __fmul_rn(tt, tt);
                acc[t]   = fadd_via_fma(sq, acc[t]);
            }
        }
    }

    float ed[IT];
#pragma unroll
    for (int t = 0; t < IT; t++) {
        float d = __fadd_rn(acc[t], 1e-10f);
        float e = __fdiv_rn(1.0f, d);
        if (j == i0 + t) e = 0.0f;           // offdiag mask before the max
        ed[t] = e;
        float m = e;
#pragma unroll
        for (int o = 16; o > 0; o >>= 1)
            m = fmaxf(m, __shfl_xor_sync(0xFFFFFFFFu, m, o));
        if ((threadIdx.x & 31) == 0) s_max[t][threadIdx.x >> 5] = m;
    }
    __syncthreads();

#pragma unroll
    for (int t = 0; t < IT; t++) {
        float m = s_max[t][0];
#pragma unroll
        for (int w = 1; w < 16; w++) m = fmaxf(m, s_max[t][w]);

        const bool diag = (j == i0 + t);
        // prefilter: e <= 4.5e-5*m provably implies 2l <= -20 (certain 0);
        // survivors run the exact div+logf+test, so decisions are bit-identical
        // to the unfiltered reference path.
        if (diag || ed[t] > __fmul_rn(4.5e-5f, m)) {
            float p;
            if (diag) p = 0.99f;                             // (0 + 1)*0.99
            else      p = __fmul_rn(__fdiv_rn(ed[t], m), 0.99f);
            float l = logf(__fdiv_rn(p, __fsub_rn(1.0f, p)));
            if (!(__fadd_rn(l, l) <= -20.0f)) {              // uncertain
                uint32_t flat = (uint32_t)(((b * KQ + (i0 + t)) * KQ + j) * 2);
                float g0 = gumbel_from_bits(jax_bits_partitionable(flat));
                float g1 = gumbel_from_bits(jax_bits_partitionable(flat + 1u));
                // argmax over {l+g0, -l+g1}; tie -> index 0 -> sample = 1
                if (__fadd_rn(l, g0) >= __fadd_rn(-l, g1))
                    atomicAdd(out + (i0 + t) * KQ + j, 0.125f);  // exact 1/8 units
            }
        }
    }
}

// ---------------------------------------------------------------------------
extern "C" void kernel_launch(void* const* d_in, const int* in_sizes, int n_in,
                              void* d_out, int out_size) {
    const float* amp = (const float*)d_in[0];   // (B, C, K)
    const float* ph  = (const float*)d_in[1];   // (B, C, K)
    const float* A   = (const float*)d_in[2];   // (K, K)
    const float* wa  = (const float*)d_in[3];   // scalar
    const float* wp  = (const float*)d_in[4];   // scalar
    float* out = (float*)d_out;                  // (K, K)

    k_init<<<KQ * KQ / 512, 512>>>(out);
    dim3 g1(KQ / IT, BQ);
    k_fused<<<g1, KQ>>>(amp, ph, A, wa, wp, out);
}

// round 9
// speedup vs baseline: 1.2751x; 1.2751x over previous
#include <cuda_runtime.h>
#include <cstdint>

#define BQ 8
#define CQ 32
#define KQ 512
#define IT 4            // i-rows per block in kernel 1 (one float4)

// Uncertain-decision list (worst case B*K*K entries)
__device__ uint32_t g_cnt;
__device__ uint2    g_ent[BQ * KQ * KQ];   // .x = (b<<18)|(i<<9)|j, .y = logit bits

// ---------------------------------------------------------------------------
// Threefry-2x32, key (0, 42); partitionable scheme: bits(idx) = o0 ^ o1 of
// threefry(key, (0, idx)).
// ---------------------------------------------------------------------------
__device__ __forceinline__ uint32_t rotl32(uint32_t x, int r) {
    return (x << r) | (x >> (32 - r));
}
__device__ __forceinline__ void threefry_0_42(uint32_t x0, uint32_t x1,
                                              uint32_t& o0, uint32_t& o1) {
    const uint32_t ks0 = 0u, ks1 = 42u, ks2 = 0u ^ 42u ^ 0x1BD11BDAu;
    x0 += ks0; x1 += ks1;
    x0 += x1; x1 = rotl32(x1, 13); x1 ^= x0;
    x0 += x1; x1 = rotl32(x1, 15); x1 ^= x0;
    x0 += x1; x1 = rotl32(x1, 26); x1 ^= x0;
    x0 += x1; x1 = rotl32(x1, 6);  x1 ^= x0;
    x0 += ks1; x1 += ks2 + 1u;
    x0 += x1; x1 = rotl32(x1, 17); x1 ^= x0;
    x0 += x1; x1 = rotl32(x1, 29); x1 ^= x0;
    x0 += x1; x1 = rotl32(x1, 16); x1 ^= x0;
    x0 += x1; x1 = rotl32(x1, 24); x1 ^= x0;
    x0 += ks2; x1 += ks0 + 2u;
    x0 += x1; x1 = rotl32(x1, 13); x1 ^= x0;
    x0 += x1; x1 = rotl32(x1, 15); x1 ^= x0;
    x0 += x1; x1 = rotl32(x1, 26); x1 ^= x0;
    x0 += x1; x1 = rotl32(x1, 6);  x1 ^= x0;
    x0 += ks0; x1 += ks1 + 3u;
    x0 += x1; x1 = rotl32(x1, 17); x1 ^= x0;
    x0 += x1; x1 = rotl32(x1, 29); x1 ^= x0;
    x0 += x1; x1 = rotl32(x1, 16); x1 ^= x0;
    x0 += x1; x1 = rotl32(x1, 24); x1 ^= x0;
    x0 += ks1; x1 += ks2 + 4u;
    x0 += x1; x1 = rotl32(x1, 13); x1 ^= x0;
    x0 += x1; x1 = rotl32(x1, 15); x1 ^= x0;
    x0 += x1; x1 = rotl32(x1, 26); x1 ^= x0;
    x0 += x1; x1 = rotl32(x1, 6);  x1 ^= x0;
    x0 += ks2; x1 += ks0 + 5u;
    o0 = x0; o1 = x1;
}
__device__ __forceinline__ uint32_t jax_bits_partitionable(uint32_t idx) {
    uint32_t o0, o1;
    threefry_0_42(0u, idx, o0, o1);
    return o0 ^ o1;
}
__device__ __forceinline__ float gumbel_from_bits(uint32_t bits) {
    float f = __uint_as_float((bits >> 9) | 0x3F800000u) - 1.0f;
    float u = fmaxf(__fadd_rn(f, 1e-10f), 1e-10f);
    return -logf(-logf(u));
}

// add-class ops as FFMA intrinsics (bit-exact: +-1.0 product exact, single rn)
__device__ __forceinline__ float fsub_via_fma(float a, float b) {
    return __fmaf_rn(b, -1.0f, a);
}
__device__ __forceinline__ float fadd_via_fma(float a, float b) {
    return __fmaf_rn(a, 1.0f, b);
}

// ---------------------------------------------------------------------------
// Kernel 1: logits + uncertain-list compaction.
// grid (KQ/IT, BQ) = (128, 8), 512 threads (thread = j).
// Issue-bound (R8 profile): minimize instruction count — float4 smem loads
// (one LDS.128 per array per c), fully unrolled c-loop (immediate addresses).
// ---------------------------------------------------------------------------
__global__ void __launch_bounds__(KQ)
k_logit(const float* __restrict__ amp, const float* __restrict__ ph,
        const float* __restrict__ A,
        const float* __restrict__ wa_p, const float* __restrict__ wp_p) {
    const int b  = blockIdx.y;
    const int i0 = blockIdx.x * IT;
    const int j  = threadIdx.x;

    __shared__ float4   s_a4[CQ];
    __shared__ float4   s_p4[CQ];
    __shared__ float    s_max[IT][16];
    __shared__ uint32_t s_cnt;
    __shared__ uint32_t s_base;

    const float wa = wa_p[0];
    const float wp = wp_p[0];
    // wa = wp = 0.5 fast path is bit-exact: rn(0.5*x) exact (pow-2 scale), so
    // f = rn(0.5*ad + 0.5*pd) = 0.5*rn(ad+pd) and rn(f*Ajj) = rn(s*(0.5*Ajj)).
    const bool half = (__float_as_uint(wa) == 0x3F000000u) &&
                      (__float_as_uint(wp) == 0x3F000000u);

    if (threadIdx.x == 0) s_cnt = 0;
    if (threadIdx.x < IT * CQ) {
        int t = threadIdx.x % IT;
        int c = threadIdx.x / IT;
        ((float*)&s_a4[c])[t] = amp[(b * CQ + c) * KQ + i0 + t];
        ((float*)&s_p4[c])[t] = ph [(b * CQ + c) * KQ + i0 + t];
    }
    __syncthreads();

    const float Ajj = A[j * KQ + j];
    const float Aj2 = __fmul_rn(0.5f, Ajj);   // exact

    float acc[IT];
#pragma unroll
    for (int t = 0; t < IT; t++) acc[t] = 0.0f;

    const float* ap = amp + (size_t)b * CQ * KQ + j;
    const float* pp = ph  + (size_t)b * CQ * KQ + j;

    if (half) {
#pragma unroll
        for (int c = 0; c < CQ; c++) {
            float aj = ap[c * KQ];
            float pj = pp[c * KQ];
            float4 va = s_a4[c];       // 1x LDS.128, warp-broadcast
            float4 vp = s_p4[c];
            float sa[IT] = {va.x, va.y, va.z, va.w};
            float sp[IT] = {vp.x, vp.y, vp.z, vp.w};
#pragma unroll
            for (int t = 0; t < IT; t++) {
                float ad = fsub_via_fma(sa[t], aj);    // rn(ai - aj)
                float pd = fsub_via_fma(sp[t], pj);    // rn(pi - pj)
                float s  = fadd_via_fma(ad, pd);       // = 2*f bit-exactly
                float tt = __fmul_rn(s, Aj2);          // = rn(f*Ajj)
                float sq = __fmul_rn(tt, tt);
                acc[t]   = fadd_via_fma(sq, acc[t]);
            }
        }
    } else {
#pragma unroll
        for (int c = 0; c < CQ; c++) {
            float aj = ap[c * KQ];
            float pj = pp[c * KQ];
            float4 va = s_a4[c];
            float4 vp = s_p4[c];
            float sa[IT] = {va.x, va.y, va.z, va.w};
            float sp[IT] = {vp.x, vp.y, vp.z, vp.w};
#pragma unroll
            for (int t = 0; t < IT; t++) {
                float ad = fsub_via_fma(sa[t], aj);
                float pd = fsub_via_fma(sp[t], pj);
                float f  = fadd_via_fma(__fmul_rn(wa, ad), __fmul_rn(wp, pd));
                float tt = __fmul_rn(f, Ajj);
                float sq = __fmul_rn(tt, tt);
                acc[t]   = fadd_via_fma(sq, acc[t]);
            }
        }
    }

    float ed[IT];
#pragma unroll
    for (int t = 0; t < IT; t++) {
        float d = __fadd_rn(acc[t], 1e-10f);
        float e = __fdiv_rn(1.0f, d);
        if (j == i0 + t) e = 0.0f;           // offdiag mask before the max
        ed[t] = e;
        float m = e;
#pragma unroll
        for (int o = 16; o > 0; o >>= 1)
            m = fmaxf(m, __shfl_xor_sync(0xFFFFFFFFu, m, o));
        if ((threadIdx.x & 31) == 0) s_max[t][threadIdx.x >> 5] = m;
    }
    __syncthreads();

    float lg[IT];
    int nunc = 0;
    int tlist[IT];
#pragma unroll
    for (int t = 0; t < IT; t++) {
        float m = s_max[t][0];
#pragma unroll
        for (int w = 1; w < 16; w++) m = fmaxf(m, s_max[t][w]);

        if (j == i0 + t) {
            // diag: p = 0.99 exactly
            float l = logf(__fdiv_rn(0.99f, __fsub_rn(1.0f, 0.99f)));
            lg[t] = l; tlist[nunc++] = t;
        } else if (ed[t] > __fmul_rn(4.5e-5f, m)) {
            // prefilter: e <= 4.5e-5*m provably implies 2l <= -20 (certain 0);
            // survivors still run the exact div+logf+test, so the list is
            // bit-identical to the unfiltered version.
            float p = __fmul_rn(__fdiv_rn(ed[t], m), 0.99f);
            float l = logf(__fdiv_rn(p, __fsub_rn(1.0f, p)));
            if (!(__fadd_rn(l, l) <= -20.0f)) { lg[t] = l; tlist[nunc] = t; nunc++; }
        }
    }

    int rank = 0;
    if (nunc > 0) rank = atomicAdd(&s_cnt, (uint32_t)nunc);
    __syncthreads();
    if (threadIdx.x == 0 && s_cnt > 0) s_base = atomicAdd(&g_cnt, s_cnt);
    __syncthreads();

    for (int q = 0; q < nunc; q++) {
        int t = tlist[q];
        uint2 ent;
        ent.x = ((uint32_t)b << 18) | ((uint32_t)(i0 + t) << 9) | (uint32_t)j;
        ent.y = __float_as_uint(lg[t]);
        g_ent[s_base + rank + q] = ent;
    }
}

// ---------------------------------------------------------------------------
// Kernel 2: process the compacted uncertain list, scatter exact 1/8 adds.
// ---------------------------------------------------------------------------
__global__ void __launch_bounds__(256)
k_sample2(float* __restrict__ out) {
    const uint32_t n = g_cnt;
    const uint32_t stride = gridDim.x * blockDim.x;
    for (uint32_t k = blockIdx.x * blockDim.x + threadIdx.x; k < n; k += stride) {
        uint2 ent = g_ent[k];
        float l = __uint_as_float(ent.y);
        uint32_t flat = ent.x << 1;      // flat index into (B,K,K,2)
        float g0 = gumbel_from_bits(jax_bits_partitionable(flat));
        float g1 = gumbel_from_bits(jax_bits_partitionable(flat + 1u));
        // argmax over {l+g0, -l+g1}; tie -> index 0 -> sample = 1
        if (__fadd_rn(l, g0) >= __fadd_rn(-l, g1))
            atomicAdd(out + (ent.x & 0x3FFFFu), 0.125f);   // exact multiples of 1/8
    }
}

// ---------------------------------------------------------------------------
extern "C" void kernel_launch(void* const* d_in, const int* in_sizes, int n_in,
                              void* d_out, int out_size) {
    const float* amp = (const float*)d_in[0];   // (B, C, K)
    const float* ph  = (const float*)d_in[1];   // (B, C, K)
    const float* A   = (const float*)d_in[2];   // (K, K)
    const float* wa  = (const float*)d_in[3];   // scalar
    const float* wp  = (const float*)d_in[4];   // scalar
    float* out = (float*)d_out;                  // (K, K)

    void* cnt_addr = nullptr;
    cudaGetSymbolAddress(&cnt_addr, g_cnt);
    cudaMemsetAsync(cnt_addr, 0, sizeof(uint32_t));
    cudaMemsetAsync(out, 0, KQ * KQ * sizeof(float));

    dim3 g1(KQ / IT, BQ);
    k_logit<<<g1, KQ>>>(amp, ph, A, wa, wp);
    k_sample2<<<1024, 256>>>(out);
}

// round 10
// speedup vs baseline: 1.2896x; 1.0114x over previous
#include <cuda_runtime.h>
#include <cstdint>

#define BQ 8
#define CQ 32
#define KQ 512
#define IT 4            // i-rows per block in kernel 1 (one float4)

// Uncertain-decision list (worst case B*K*K entries)
__device__ uint32_t g_cnt;
__device__ uint2    g_ent[BQ * KQ * KQ];   // .x = (b<<18)|(i<<9)|j, .y = logit bits

// ---------------------------------------------------------------------------
// Threefry-2x32, key (0, 42); partitionable scheme: bits(idx) = o0 ^ o1 of
// threefry(key, (0, idx)).
// ---------------------------------------------------------------------------
__device__ __forceinline__ uint32_t rotl32(uint32_t x, int r) {
    return (x << r) | (x >> (32 - r));
}
__device__ __forceinline__ void threefry_0_42(uint32_t x0, uint32_t x1,
                                              uint32_t& o0, uint32_t& o1) {
    const uint32_t ks0 = 0u, ks1 = 42u, ks2 = 0u ^ 42u ^ 0x1BD11BDAu;
    x0 += ks0; x1 += ks1;
    x0 += x1; x1 = rotl32(x1, 13); x1 ^= x0;
    x0 += x1; x1 = rotl32(x1, 15); x1 ^= x0;
    x0 += x1; x1 = rotl32(x1, 26); x1 ^= x0;
    x0 += x1; x1 = rotl32(x1, 6);  x1 ^= x0;
    x0 += ks1; x1 += ks2 + 1u;
    x0 += x1; x1 = rotl32(x1, 17); x1 ^= x0;
    x0 += x1; x1 = rotl32(x1, 29); x1 ^= x0;
    x0 += x1; x1 = rotl32(x1, 16); x1 ^= x0;
    x0 += x1; x1 = rotl32(x1, 24); x1 ^= x0;
    x0 += ks2; x1 += ks0 + 2u;
    x0 += x1; x1 = rotl32(x1, 13); x1 ^= x0;
    x0 += x1; x1 = rotl32(x1, 15); x1 ^= x0;
    x0 += x1; x1 = rotl32(x1, 26); x1 ^= x0;
    x0 += x1; x1 = rotl32(x1, 6);  x1 ^= x0;
    x0 += ks0; x1 += ks1 + 3u;
    x0 += x1; x1 = rotl32(x1, 17); x1 ^= x0;
    x0 += x1; x1 = rotl32(x1, 29); x1 ^= x0;
    x0 += x1; x1 = rotl32(x1, 16); x1 ^= x0;
    x0 += x1; x1 = rotl32(x1, 24); x1 ^= x0;
    x0 += ks1; x1 += ks2 + 4u;
    x0 += x1; x1 = rotl32(x1, 13); x1 ^= x0;
    x0 += x1; x1 = rotl32(x1, 15); x1 ^= x0;
    x0 += x1; x1 = rotl32(x1, 26); x1 ^= x0;
    x0 += x1; x1 = rotl32(x1, 6);  x1 ^= x0;
    x0 += ks2; x1 += ks0 + 5u;
    o0 = x0; o1 = x1;
}
__device__ __forceinline__ uint32_t jax_bits_partitionable(uint32_t idx) {
    uint32_t o0, o1;
    threefry_0_42(0u, idx, o0, o1);
    return o0 ^ o1;
}
__device__ __forceinline__ float gumbel_from_bits(uint32_t bits) {
    float f = __uint_as_float((bits >> 9) | 0x3F800000u) - 1.0f;
    float u = fmaxf(__fadd_rn(f, 1e-10f), 1e-10f);
    return -logf(-logf(u));
}

// Genuine FFMA the compiler cannot fold back to FADD (pipe-balance lever):
// rn(a + b) == fma(a, 1.0, b) — product exact, single rounding, bit-exact.
__device__ __forceinline__ float ffma_add_asm(float a, float b) {
    float d;
    asm("fma.rn.f32 %0, %1, 0f3F800000, %2;" : "=f"(d) : "f"(a), "f"(b));
    return d;
}

// ---------------------------------------------------------------------------
// Kernel 1: logits + uncertain-list compaction.
// grid (KQ/IT, BQ) = (128, 8), 512 threads (thread = j).
// Pipe-balanced inner loop: alu pipe {ad, pd, acc} (3 FADD = 6 cyc),
// fma pipe {s(FFMA-asm), tt, sq} (6 cyc) — vs 8-cyc alu bound before.
// ---------------------------------------------------------------------------
__global__ void __launch_bounds__(KQ)
k_logit(const float* __restrict__ amp, const float* __restrict__ ph,
        const float* __restrict__ A,
        const float* __restrict__ wa_p, const float* __restrict__ wp_p) {
    const int b  = blockIdx.y;
    const int i0 = blockIdx.x * IT;
    const int j  = threadIdx.x;

    __shared__ float4   s_a4[CQ];
    __shared__ float4   s_p4[CQ];
    __shared__ float    s_max[IT][16];
    __shared__ uint32_t s_cnt;
    __shared__ uint32_t s_base;

    const float wa = wa_p[0];
    const float wp = wp_p[0];
    // wa = wp = 0.5 fast path is bit-exact: rn(0.5*x) exact (pow-2 scale), so
    // f = rn(0.5*ad + 0.5*pd) = 0.5*rn(ad+pd) and rn(f*Ajj) = rn(s*(0.5*Ajj)).
    const bool half = (__float_as_uint(wa) == 0x3F000000u) &&
                      (__float_as_uint(wp) == 0x3F000000u);

    if (threadIdx.x == 0) s_cnt = 0;
    if (threadIdx.x < IT * CQ) {
        int t = threadIdx.x % IT;
        int c = threadIdx.x / IT;
        ((float*)&s_a4[c])[t] = amp[(b * CQ + c) * KQ + i0 + t];
        ((float*)&s_p4[c])[t] = ph [(b * CQ + c) * KQ + i0 + t];
    }
    __syncthreads();

    const float Ajj = A[j * KQ + j];
    const float Aj2 = __fmul_rn(0.5f, Ajj);   // exact

    float acc[IT];
#pragma unroll
    for (int t = 0; t < IT; t++) acc[t] = 0.0f;

    const float* ap = amp + (size_t)b * CQ * KQ + j;
    const float* pp = ph  + (size_t)b * CQ * KQ + j;

    if (half) {
#pragma unroll
        for (int c = 0; c < CQ; c++) {
            float aj = ap[c * KQ];
            float pj = pp[c * KQ];
            float4 va = s_a4[c];       // 1x LDS.128, warp-broadcast
            float4 vp = s_p4[c];
            float sa[IT] = {va.x, va.y, va.z, va.w};
            float sp[IT] = {vp.x, vp.y, vp.z, vp.w};
#pragma unroll
            for (int t = 0; t < IT; t++) {
                float ad = __fsub_rn(sa[t], aj);       // FADD   (alu pipe)
                float pd = __fsub_rn(sp[t], pj);       // FADD   (alu pipe)
                float s  = ffma_add_asm(ad, pd);       // FFMA   (fma pipe) = 2*f
                float tt = __fmul_rn(s, Aj2);          // FMUL   (fma pipe) = rn(f*Ajj)
                float sq = __fmul_rn(tt, tt);          // FMUL   (fma pipe)
                acc[t]   = __fadd_rn(sq, acc[t]);      // FADD   (alu pipe)
            }
        }
    } else {
#pragma unroll
        for (int c = 0; c < CQ; c++) {
            float aj = ap[c * KQ];
            float pj = pp[c * KQ];
            float4 va = s_a4[c];
            float4 vp = s_p4[c];
            float sa[IT] = {va.x, va.y, va.z, va.w};
            float sp[IT] = {vp.x, vp.y, vp.z, vp.w};
#pragma unroll
            for (int t = 0; t < IT; t++) {
                float ad = __fsub_rn(sa[t], aj);
                float pd = __fsub_rn(sp[t], pj);
                float f  = ffma_add_asm(__fmul_rn(wa, ad), __fmul_rn(wp, pd));
                float tt = __fmul_rn(f, Ajj);
                float sq = __fmul_rn(tt, tt);
                acc[t]   = __fadd_rn(sq, acc[t]);
            }
        }
    }

    float ed[IT];
#pragma unroll
    for (int t = 0; t < IT; t++) {
        float d = __fadd_rn(acc[t], 1e-10f);
        float e = __fdiv_rn(1.0f, d);
        if (j == i0 + t) e = 0.0f;           // offdiag mask before the max
        ed[t] = e;
        float m = e;
#pragma unroll
        for (int o = 16; o > 0; o >>= 1)
            m = fmaxf(m, __shfl_xor_sync(0xFFFFFFFFu, m, o));
        if ((threadIdx.x & 31) == 0) s_max[t][threadIdx.x >> 5] = m;
    }
    __syncthreads();

    float lg[IT];
    int nunc = 0;
    int tlist[IT];
#pragma unroll
    for (int t = 0; t < IT; t++) {
        float m = s_max[t][0];
#pragma unroll
        for (int w = 1; w < 16; w++) m = fmaxf(m, s_max[t][w]);

        if (j == i0 + t) {
            // diag: p = 0.99 exactly
            float l = logf(__fdiv_rn(0.99f, __fsub_rn(1.0f, 0.99f)));
            lg[t] = l; tlist[nunc++] = t;
        } else if (ed[t] > __fmul_rn(4.5e-5f, m)) {
            // prefilter: e <= 4.5e-5*m provably implies 2l <= -20 (certain 0);
            // survivors still run the exact div+logf+test, so the list is
            // bit-identical to the unfiltered version.
            float p = __fmul_rn(__fdiv_rn(ed[t], m), 0.99f);
            float l = logf(__fdiv_rn(p, __fsub_rn(1.0f, p)));
            if (!(__fadd_rn(l, l) <= -20.0f)) { lg[t] = l; tlist[nunc] = t; nunc++; }
        }
    }

    int rank = 0;
    if (nunc > 0) rank = atomicAdd(&s_cnt, (uint32_t)nunc);
    __syncthreads();
    if (threadIdx.x == 0 && s_cnt > 0) s_base = atomicAdd(&g_cnt, s_cnt);
    __syncthreads();

    for (int q = 0; q < nunc; q++) {
        int t = tlist[q];
        uint2 ent;
        ent.x = ((uint32_t)b << 18) | ((uint32_t)(i0 + t) << 9) | (uint32_t)j;
        ent.y = __float_as_uint(lg[t]);
        g_ent[s_base + rank + q] = ent;
    }
}

// ---------------------------------------------------------------------------
// Kernel 2: process the compacted uncertain list, scatter exact 1/8 adds.
// ---------------------------------------------------------------------------
__global__ void __launch_bounds__(256)
k_sample2(float* __restrict__ out) {
    const uint32_t n = g_cnt;
    const uint32_t stride = gridDim.x * blockDim.x;
    for (uint32_t k = blockIdx.x * blockDim.x + threadIdx.x; k < n; k += stride) {
        uint2 ent = g_ent[k];
        float l = __uint_as_float(ent.y);
        uint32_t flat = ent.x << 1;      // flat index into (B,K,K,2)
        float g0 = gumbel_from_bits(jax_bits_partitionable(flat));
        float g1 = gumbel_from_bits(jax_bits_partitionable(flat + 1u));
        // argmax over {l+g0, -l+g1}; tie -> index 0 -> sample = 1
        if (__fadd_rn(l, g0) >= __fadd_rn(-l, g1))
            atomicAdd(out + (ent.x & 0x3FFFFu), 0.125f);   // exact multiples of 1/8
    }
}

// ---------------------------------------------------------------------------
extern "C" void kernel_launch(void* const* d_in, const int* in_sizes, int n_in,
                              void* d_out, int out_size) {
    const float* amp = (const float*)d_in[0];   // (B, C, K)
    const float* ph  = (const float*)d_in[1];   // (B, C, K)
    const float* A   = (const float*)d_in[2];   // (K, K)
    const float* wa  = (const float*)d_in[3];   // scalar
    const float* wp  = (const float*)d_in[4];   // scalar
    float* out = (float*)d_out;                  // (K, K)

    void* cnt_addr = nullptr;
    cudaGetSymbolAddress(&cnt_addr, g_cnt);
    cudaMemsetAsync(cnt_addr, 0, sizeof(uint32_t));
    cudaMemsetAsync(out, 0, KQ * KQ * sizeof(float));

    dim3 g1(KQ / IT, BQ);
    k_logit<<<g1, KQ>>>(amp, ph, A, wa, wp);
    k_sample2<<<1024, 256>>>(out);
}

// round 11
// speedup vs baseline: 1.4187x; 1.1001x over previous
#include <cuda_runtime.h>
#include <cstdint>

#define BQ 8
#define CQ 32
#define KQ 512
#define IT 4            // i-rows per block (one float4)
#define MAXL (IT * KQ)  // worst-case uncertain entries per block

// ---------------------------------------------------------------------------
// Threefry-2x32, key (0, 42); partitionable scheme: bits(idx) = o0 ^ o1 of
// threefry(key, (0, idx)).
// ---------------------------------------------------------------------------
__device__ __forceinline__ uint32_t rotl32(uint32_t x, int r) {
    return (x << r) | (x >> (32 - r));
}
__device__ __forceinline__ void threefry_0_42(uint32_t x0, uint32_t x1,
                                              uint32_t& o0, uint32_t& o1) {
    const uint32_t ks0 = 0u, ks1 = 42u, ks2 = 0u ^ 42u ^ 0x1BD11BDAu;
    x0 += ks0; x1 += ks1;
    x0 += x1; x1 = rotl32(x1, 13); x1 ^= x0;
    x0 += x1; x1 = rotl32(x1, 15); x1 ^= x0;
    x0 += x1; x1 = rotl32(x1, 26); x1 ^= x0;
    x0 += x1; x1 = rotl32(x1, 6);  x1 ^= x0;
    x0 += ks1; x1 += ks2 + 1u;
    x0 += x1; x1 = rotl32(x1, 17); x1 ^= x0;
    x0 += x1; x1 = rotl32(x1, 29); x1 ^= x0;
    x0 += x1; x1 = rotl32(x1, 16); x1 ^= x0;
    x0 += x1; x1 = rotl32(x1, 24); x1 ^= x0;
    x0 += ks2; x1 += ks0 + 2u;
    x0 += x1; x1 = rotl32(x1, 13); x1 ^= x0;
    x0 += x1; x1 = rotl32(x1, 15); x1 ^= x0;
    x0 += x1; x1 = rotl32(x1, 26); x1 ^= x0;
    x0 += x1; x1 = rotl32(x1, 6);  x1 ^= x0;
    x0 += ks0; x1 += ks1 + 3u;
    x0 += x1; x1 = rotl32(x1, 17); x1 ^= x0;
    x0 += x1; x1 = rotl32(x1, 29); x1 ^= x0;
    x0 += x1; x1 = rotl32(x1, 16); x1 ^= x0;
    x0 += x1; x1 = rotl32(x1, 24); x1 ^= x0;
    x0 += ks1; x1 += ks2 + 4u;
    x0 += x1; x1 = rotl32(x1, 13); x1 ^= x0;
    x0 += x1; x1 = rotl32(x1, 15); x1 ^= x0;
    x0 += x1; x1 = rotl32(x1, 26); x1 ^= x0;
    x0 += x1; x1 = rotl32(x1, 6);  x1 ^= x0;
    x0 += ks2; x1 += ks0 + 5u;
    o0 = x0; o1 = x1;
}
__device__ __forceinline__ uint32_t jax_bits_partitionable(uint32_t idx) {
    uint32_t o0, o1;
    threefry_0_42(0u, idx, o0, o1);
    return o0 ^ o1;
}
__device__ __forceinline__ float gumbel_from_bits(uint32_t bits) {
    float f = __uint_as_float((bits >> 9) | 0x3F800000u) - 1.0f;
    float u = fmaxf(__fadd_rn(f, 1e-10f), 1e-10f);
    return -logf(-logf(u));
}

// Genuine FFMA (unfoldable) — bit-exact rn(a+b): product a*1 exact, single rn.
__device__ __forceinline__ float ffma_add_asm(float a, float b) {
    float d;
    asm("fma.rn.f32 %0, %1, 0f3F800000, %2;" : "=f"(d) : "f"(a), "f"(b));
    return d;
}

// ---------------------------------------------------------------------------
// Single fused kernel: dist -> rowmax -> logit -> BLOCK-LOCAL compaction ->
// dense in-block gumbel sampling -> atomic 1/8 adds into out.
// grid (KQ/IT, BQ) = (128, 8), 512 threads (thread = j).
// ---------------------------------------------------------------------------
__global__ void __launch_bounds__(KQ)
k_logit(const float* __restrict__ amp, const float* __restrict__ ph,
        const float* __restrict__ A,
        const float* __restrict__ wa_p, const float* __restrict__ wp_p,
        float* __restrict__ out) {
    const int b  = blockIdx.y;
    const int i0 = blockIdx.x * IT;
    const int j  = threadIdx.x;

    __shared__ float4   s_a4[CQ];
    __shared__ float4   s_p4[CQ];
    __shared__ float    s_max[IT][16];
    __shared__ uint32_t s_cnt;
    __shared__ uint32_t s_key[MAXL];   // flat (b*K+i)*K+j
    __shared__ float    s_lg [MAXL];   // logit

    const float wa = wa_p[0];
    const float wp = wp_p[0];
    // wa = wp = 0.5 fast path is bit-exact: rn(0.5*x) exact (pow-2 scale), so
    // f = rn(0.5*ad + 0.5*pd) = 0.5*rn(ad+pd) and rn(f*Ajj) = rn(s*(0.5*Ajj)).
    const bool half = (__float_as_uint(wa) == 0x3F000000u) &&
                      (__float_as_uint(wp) == 0x3F000000u);

    if (threadIdx.x == 0) s_cnt = 0;
    if (threadIdx.x < IT * CQ) {
        int t = threadIdx.x % IT;
        int c = threadIdx.x / IT;
        ((float*)&s_a4[c])[t] = amp[(b * CQ + c) * KQ + i0 + t];
        ((float*)&s_p4[c])[t] = ph [(b * CQ + c) * KQ + i0 + t];
    }
    __syncthreads();

    const float Ajj = A[j * KQ + j];
    const float Aj2 = __fmul_rn(0.5f, Ajj);   // exact

    float acc[IT];
#pragma unroll
    for (int t = 0; t < IT; t++) acc[t] = 0.0f;

    const float* ap = amp + (size_t)b * CQ * KQ + j;
    const float* pp = ph  + (size_t)b * CQ * KQ + j;

    if (half) {
#pragma unroll
        for (int c = 0; c < CQ; c++) {
            float aj = ap[c * KQ];
            float pj = pp[c * KQ];
            float4 va = s_a4[c];       // 1x LDS.128, warp-broadcast
            float4 vp = s_p4[c];
            float sa[IT] = {va.x, va.y, va.z, va.w};
            float sp[IT] = {vp.x, vp.y, vp.z, vp.w};
#pragma unroll
            for (int t = 0; t < IT; t++) {
                float ad = __fsub_rn(sa[t], aj);       // rn(ai - aj)
                float pd = __fsub_rn(sp[t], pj);       // rn(pi - pj)
                float s  = ffma_add_asm(ad, pd);       // = 2*f bit-exactly
                float tt = __fmul_rn(s, Aj2);          // = rn(f*Ajj)
                float sq = __fmul_rn(tt, tt);
                acc[t]   = __fadd_rn(sq, acc[t]);
            }
        }
    } else {
#pragma unroll
        for (int c = 0; c < CQ; c++) {
            float aj = ap[c * KQ];
            float pj = pp[c * KQ];
            float4 va = s_a4[c];
            float4 vp = s_p4[c];
            float sa[IT] = {va.x, va.y, va.z, va.w};
            float sp[IT] = {vp.x, vp.y, vp.z, vp.w};
#pragma unroll
            for (int t = 0; t < IT; t++) {
                float ad = __fsub_rn(sa[t], aj);
                float pd = __fsub_rn(sp[t], pj);
                float f  = ffma_add_asm(__fmul_rn(wa, ad), __fmul_rn(wp, pd));
                float tt = __fmul_rn(f, Ajj);
                float sq = __fmul_rn(tt, tt);
                acc[t]   = __fadd_rn(sq, acc[t]);
            }
        }
    }

    float ed[IT];
#pragma unroll
    for (int t = 0; t < IT; t++) {
        float d = __fadd_rn(acc[t], 1e-10f);
        float e = __fdiv_rn(1.0f, d);
        if (j == i0 + t) e = 0.0f;           // offdiag mask before the max
        ed[t] = e;
        float m = e;
#pragma unroll
        for (int o = 16; o > 0; o >>= 1)
            m = fmaxf(m, __shfl_xor_sync(0xFFFFFFFFu, m, o));
        if ((threadIdx.x & 31) == 0) s_max[t][threadIdx.x >> 5] = m;
    }
    __syncthreads();

    // logits + block-local compaction of uncertain decisions
#pragma unroll
    for (int t = 0; t < IT; t++) {
        float m = s_max[t][0];
#pragma unroll
        for (int w = 1; w < 16; w++) m = fmaxf(m, s_max[t][w]);

        const bool diag = (j == i0 + t);
        // prefilter: e <= 4.5e-5*m provably implies 2l <= -20 (certain 0);
        // survivors run the exact div+logf+test, so the uncertain set is
        // bit-identical to the unfiltered reference path.
        if (diag || ed[t] > __fmul_rn(4.5e-5f, m)) {
            float p;
            if (diag) p = 0.99f;                              // (0 + 1)*0.99
            else      p = __fmul_rn(__fdiv_rn(ed[t], m), 0.99f);
            float l = logf(__fdiv_rn(p, __fsub_rn(1.0f, p)));
            if (!(__fadd_rn(l, l) <= -20.0f)) {               // uncertain
                uint32_t r = atomicAdd(&s_cnt, 1u);
                s_key[r] = ((uint32_t)b << 18) | ((uint32_t)(i0 + t) << 9) | (uint32_t)j;
                s_lg [r] = l;
            }
        }
    }
    __syncthreads();

    // dense drain of the block's uncertain list (warp-efficient gumbel work)
    const uint32_t n = s_cnt;
    for (uint32_t k = threadIdx.x; k < n; k += KQ) {
        uint32_t key = s_key[k];
        float l = s_lg[k];
        uint32_t flat = key << 1;      // flat index into (B,K,K,2)
        float g0 = gumbel_from_bits(jax_bits_partitionable(flat));
        float g1 = gumbel_from_bits(jax_bits_partitionable(flat + 1u));
        // argmax over {l+g0, -l+g1}; tie -> index 0 -> sample = 1
        if (__fadd_rn(l, g0) >= __fadd_rn(-l, g1))
            atomicAdd(out + (key & 0x3FFFFu), 0.125f);   // exact multiples of 1/8
    }
}

// ---------------------------------------------------------------------------
extern "C" void kernel_launch(void* const* d_in, const int* in_sizes, int n_in,
                              void* d_out, int out_size) {
    const float* amp = (const float*)d_in[0];   // (B, C, K)
    const float* ph  = (const float*)d_in[1];   // (B, C, K)
    const float* A   = (const float*)d_in[2];   // (K, K)
    const float* wa  = (const float*)d_in[3];   // scalar
    const float* wp  = (const float*)d_in[4];   // scalar
    float* out = (float*)d_out;                  // (K, K)

    cudaMemsetAsync(out, 0, KQ * KQ * sizeof(float));
    dim3 g1(KQ / IT, BQ);
    k_logit<<<g1, KQ>>>(amp, ph, A, wa, wp, out);
}

// round 12
// speedup vs baseline: 1.6022x; 1.1293x over previous
#include <cuda_runtime.h>
#include <cstdint>

#define BQ 8
#define CQ 32
#define KQ 512
#define TI 64                       // tile side for k_dist
#define NT (KQ / TI)                // 8 tiles per side
#define NPAIR_T (NT * (NT + 1) / 2) // 36 triangular tile pairs
#define ITB 4                       // i-rows per block in k_samp
#define MAXL (ITB * KQ)

// dist scratch (B, K, K) fp32 = 8MB
__device__ float g_dist[BQ * KQ * KQ];

// ---------------------------------------------------------------------------
// Threefry-2x32, key (0, 42); partitionable: bits(idx) = o0 ^ o1.
// ---------------------------------------------------------------------------
__device__ __forceinline__ uint32_t rotl32(uint32_t x, int r) {
    return (x << r) | (x >> (32 - r));
}
__device__ __forceinline__ void threefry_0_42(uint32_t x0, uint32_t x1,
                                              uint32_t& o0, uint32_t& o1) {
    const uint32_t ks0 = 0u, ks1 = 42u, ks2 = 0u ^ 42u ^ 0x1BD11BDAu;
    x0 += ks0; x1 += ks1;
    x0 += x1; x1 = rotl32(x1, 13); x1 ^= x0;
    x0 += x1; x1 = rotl32(x1, 15); x1 ^= x0;
    x0 += x1; x1 = rotl32(x1, 26); x1 ^= x0;
    x0 += x1; x1 = rotl32(x1, 6);  x1 ^= x0;
    x0 += ks1; x1 += ks2 + 1u;
    x0 += x1; x1 = rotl32(x1, 17); x1 ^= x0;
    x0 += x1; x1 = rotl32(x1, 29); x1 ^= x0;
    x0 += x1; x1 = rotl32(x1, 16); x1 ^= x0;
    x0 += x1; x1 = rotl32(x1, 24); x1 ^= x0;
    x0 += ks2; x1 += ks0 + 2u;
    x0 += x1; x1 = rotl32(x1, 13); x1 ^= x0;
    x0 += x1; x1 = rotl32(x1, 15); x1 ^= x0;
    x0 += x1; x1 = rotl32(x1, 26); x1 ^= x0;
    x0 += x1; x1 = rotl32(x1, 6);  x1 ^= x0;
    x0 += ks0; x1 += ks1 + 3u;
    x0 += x1; x1 = rotl32(x1, 17); x1 ^= x0;
    x0 += x1; x1 = rotl32(x1, 29); x1 ^= x0;
    x0 += x1; x1 = rotl32(x1, 16); x1 ^= x0;
    x0 += x1; x1 = rotl32(x1, 24); x1 ^= x0;
    x0 += ks1; x1 += ks2 + 4u;
    x0 += x1; x1 = rotl32(x1, 13); x1 ^= x0;
    x0 += x1; x1 = rotl32(x1, 15); x1 ^= x0;
    x0 += x1; x1 = rotl32(x1, 26); x1 ^= x0;
    x0 += x1; x1 = rotl32(x1, 6);  x1 ^= x0;
    x0 += ks2; x1 += ks0 + 5u;
    o0 = x0; o1 = x1;
}
__device__ __forceinline__ uint32_t jax_bits_partitionable(uint32_t idx) {
    uint32_t o0, o1;
    threefry_0_42(0u, idx, o0, o1);
    return o0 ^ o1;
}
__device__ __forceinline__ float gumbel_from_bits(uint32_t bits) {
    float f = __uint_as_float((bits >> 9) | 0x3F800000u) - 1.0f;
    float u = fmaxf(__fadd_rn(f, 1e-10f), 1e-10f);
    return -logf(-logf(u));
}

// ---------------------------------------------------------------------------
// Kernel A: symmetric pairwise distance tiles.
// grid (NPAIR_T, BQ) = (36, 8), 256 threads; thread owns a 4x4 pair subtile.
// Off-diag tile pair (ti<tj): shared (ad,pd,s) feeds BOTH (i,j) and (j,i)
// bit-exactly (s_ji = -s_ij exactly; sign annihilated by the square):
// 9 rn-ops per 2 elements. Diagonal tiles: direct 6-op chain.
// ---------------------------------------------------------------------------
__global__ void __launch_bounds__(256)
k_dist(const float* __restrict__ amp, const float* __restrict__ ph,
       const float* __restrict__ A,
       const float* __restrict__ wa_p, const float* __restrict__ wp_p) {
    const int b = blockIdx.y;
    int x = blockIdx.x, ti = 0;
    while (x >= NT - ti) { x -= NT - ti; ti++; }   // triangular map, ti<=tj
    const int tj = ti + x;
    const int i0 = ti * TI, j0 = tj * TI;
    const int tid = threadIdx.x;
    const int si = (tid >> 4) << 2;    // sub-row base   0..60
    const int sj = (tid & 15) << 2;    // sub-col base   0..60

    __shared__ float sAi[CQ][TI], sPi[CQ][TI];
    __shared__ float sAj[CQ][TI], sPj[CQ][TI];
    __shared__ float sDi[TI], sDj[TI];   // column-diag factors

    const float wa = wa_p[0];
    const float wp = wp_p[0];
    // wa = wp = 0.5 fast path is bit-exact: rn(0.5*x) exact, so
    // rn(f*Ajj) = rn(s*(0.5*Ajj)) with s = rn(ad+pd).
    const bool half = (__float_as_uint(wa) == 0x3F000000u) &&
                      (__float_as_uint(wp) == 0x3F000000u);

    for (int f4 = tid; f4 < CQ * (TI / 4); f4 += 256) {   // 512 float4s/array
        int c  = f4 >> 4;
        int t4 = (f4 & 15) << 2;
        const float* ab = amp + (size_t)(b * CQ + c) * KQ;
        const float* pb = ph  + (size_t)(b * CQ + c) * KQ;
        *(float4*)&sAi[c][t4] = *(const float4*)&ab[i0 + t4];
        *(float4*)&sPi[c][t4] = *(const float4*)&pb[i0 + t4];
        *(float4*)&sAj[c][t4] = *(const float4*)&ab[j0 + t4];
        *(float4*)&sPj[c][t4] = *(const float4*)&pb[j0 + t4];
    }
    if (tid < TI) {
        float di = A[(size_t)(i0 + tid) * KQ + i0 + tid];
        float dj = A[(size_t)(j0 + tid) * KQ + j0 + tid];
        sDi[tid] = half ? __fmul_rn(0.5f, di) : di;   // exact halving
        sDj[tid] = half ? __fmul_rn(0.5f, dj) : dj;
    }
    __syncthreads();

    float dI[4], dJ[4];
#pragma unroll
    for (int u = 0; u < 4; u++) { dI[u] = sDi[si + u]; dJ[u] = sDj[sj + u]; }

    float accIJ[4][4], accJI[4][4];
#pragma unroll
    for (int u = 0; u < 4; u++)
#pragma unroll
        for (int v = 0; v < 4; v++) { accIJ[u][v] = 0.0f; accJI[u][v] = 0.0f; }

    if (ti != tj) {
        // ---- off-diagonal tile pair: symmetric 9-op/2-elem chain ----
        if (half) {
#pragma unroll 4
            for (int c = 0; c < CQ; c++) {
                float4 ai = *(const float4*)&sAi[c][si];
                float4 pi = *(const float4*)&sPi[c][si];
                float4 aj = *(const float4*)&sAj[c][sj];
                float4 pj = *(const float4*)&sPj[c][sj];
                float AI[4] = {ai.x, ai.y, ai.z, ai.w};
                float PI[4] = {pi.x, pi.y, pi.z, pi.w};
                float AJ[4] = {aj.x, aj.y, aj.z, aj.w};
                float PJ[4] = {pj.x, pj.y, pj.z, pj.w};
#pragma unroll
                for (int u = 0; u < 4; u++)
#pragma unroll
                    for (int v = 0; v < 4; v++) {
                        float ad = __fsub_rn(AI[u], AJ[v]);
                        float pd = __fsub_rn(PI[u], PJ[v]);
                        float s  = __fadd_rn(ad, pd);           // = 2*f exactly
                        float u1 = __fmul_rn(s, dJ[v]);         // (i,j) col-diag j
                        accIJ[u][v] = __fadd_rn(__fmul_rn(u1, u1), accIJ[u][v]);
                        float u2 = __fmul_rn(s, dI[u]);         // (j,i) col-diag i
                        accJI[v][u] = __fadd_rn(__fmul_rn(u2, u2), accJI[v][u]);
                    }
            }
        } else {
#pragma unroll 4
            for (int c = 0; c < CQ; c++) {
                float4 ai = *(const float4*)&sAi[c][si];
                float4 pi = *(const float4*)&sPi[c][si];
                float4 aj = *(const float4*)&sAj[c][sj];
                float4 pj = *(const float4*)&sPj[c][sj];
                float AI[4] = {ai.x, ai.y, ai.z, ai.w};
                float PI[4] = {pi.x, pi.y, pi.z, pi.w};
                float AJ[4] = {aj.x, aj.y, aj.z, aj.w};
                float PJ[4] = {pj.x, pj.y, pj.z, pj.w};
#pragma unroll
                for (int u = 0; u < 4; u++)
#pragma unroll
                    for (int v = 0; v < 4; v++) {
                        float ad = __fsub_rn(AI[u], AJ[v]);
                        float pd = __fsub_rn(PI[u], PJ[v]);
                        float f  = __fadd_rn(__fmul_rn(wa, ad), __fmul_rn(wp, pd));
                        float u1 = __fmul_rn(f, dJ[v]);
                        accIJ[u][v] = __fadd_rn(__fmul_rn(u1, u1), accIJ[u][v]);
                        float u2 = __fmul_rn(f, dI[u]);         // f_ji=-f; sign dies in square
                        accJI[v][u] = __fadd_rn(__fmul_rn(u2, u2), accJI[v][u]);
                    }
            }
        }
    } else {
        // ---- diagonal tile: direct chain, full coverage, no double work ----
        if (half) {
#pragma unroll 4
            for (int c = 0; c < CQ; c++) {
                float4 ai = *(const float4*)&sAi[c][si];
                float4 pi = *(const float4*)&sPi[c][si];
                float4 aj = *(const float4*)&sAj[c][sj];
                float4 pj = *(const float4*)&sPj[c][sj];
                float AI[4] = {ai.x, ai.y, ai.z, ai.w};
                float PI[4] = {pi.x, pi.y, pi.z, pi.w};
                float AJ[4] = {aj.x, aj.y, aj.z, aj.w};
                float PJ[4] = {pj.x, pj.y, pj.z, pj.w};
#pragma unroll
                for (int u = 0; u < 4; u++)
#pragma unroll
                    for (int v = 0; v < 4; v++) {
                        float ad = __fsub_rn(AI[u], AJ[v]);
                        float pd = __fsub_rn(PI[u], PJ[v]);
                        float s  = __fadd_rn(ad, pd);
                        float u1 = __fmul_rn(s, dJ[v]);
                        accIJ[u][v] = __fadd_rn(__fmul_rn(u1, u1), accIJ[u][v]);
                    }
            }
        } else {
#pragma unroll 4
            for (int c = 0; c < CQ; c++) {
                float4 ai = *(const float4*)&sAi[c][si];
                float4 pi = *(const float4*)&sPi[c][si];
                float4 aj = *(const float4*)&sAj[c][sj];
                float4 pj = *(const float4*)&sPj[c][sj];
                float AI[4] = {ai.x, ai.y, ai.z, ai.w};
                float PI[4] = {pi.x, pi.y, pi.z, pi.w};
                float AJ[4] = {aj.x, aj.y, aj.z, aj.w};
                float PJ[4] = {pj.x, pj.y, pj.z, pj.w};
#pragma unroll
                for (int u = 0; u < 4; u++)
#pragma unroll
                    for (int v = 0; v < 4; v++) {
                        float ad = __fsub_rn(AI[u], AJ[v]);
                        float pd = __fsub_rn(PI[u], PJ[v]);
                        float f  = __fadd_rn(__fmul_rn(wa, ad), __fmul_rn(wp, pd));
                        float u1 = __fmul_rn(f, dJ[v]);
                        accIJ[u][v] = __fadd_rn(__fmul_rn(u1, u1), accIJ[u][v]);
                    }
            }
        }
    }

    // write results (float4 rows; diag-tile writes accIJ only)
    float* gd = g_dist + (size_t)b * KQ * KQ;
#pragma unroll
    for (int u = 0; u < 4; u++) {
        float4 v4 = make_float4(accIJ[u][0], accIJ[u][1], accIJ[u][2], accIJ[u][3]);
        *(float4*)&gd[(size_t)(i0 + si + u) * KQ + j0 + sj] = v4;
    }
    if (ti != tj) {
#pragma unroll
        for (int v = 0; v < 4; v++) {
            float4 v4 = make_float4(accJI[v][0], accJI[v][1], accJI[v][2], accJI[v][3]);
            *(float4*)&gd[(size_t)(j0 + sj + v) * KQ + i0 + si] = v4;
        }
    }
}

// ---------------------------------------------------------------------------
// Kernel B: rowmax -> logit -> block-local compaction -> dense gumbel drain.
// grid (KQ/ITB, BQ) = (128, 8), 512 threads (thread = j).
// ---------------------------------------------------------------------------
__global__ void __launch_bounds__(KQ)
k_samp(float* __restrict__ out) {
    const int b  = blockIdx.y;
    const int i0 = blockIdx.x * ITB;
    const int j  = threadIdx.x;

    __shared__ float    s_max[ITB][16];
    __shared__ uint32_t s_cnt;
    __shared__ uint32_t s_key[MAXL];
    __shared__ float    s_lg [MAXL];

    if (threadIdx.x == 0) s_cnt = 0;

    float ed[ITB];
#pragma unroll
    for (int t = 0; t < ITB; t++) {
        float d = g_dist[(size_t)(b * KQ + i0 + t) * KQ + j];
        d = __fadd_rn(d, 1e-10f);
        float e = __fdiv_rn(1.0f, d);
        if (j == i0 + t) e = 0.0f;           // offdiag mask before the max
        ed[t] = e;
        float m = e;
#pragma unroll
        for (int o = 16; o > 0; o >>= 1)
            m = fmaxf(m, __shfl_xor_sync(0xFFFFFFFFu, m, o));
        if ((threadIdx.x & 31) == 0) s_max[t][threadIdx.x >> 5] = m;
    }
    __syncthreads();   // also orders s_cnt = 0

#pragma unroll
    for (int t = 0; t < ITB; t++) {
        float m = s_max[t][0];
#pragma unroll
        for (int w = 1; w < 16; w++) m = fmaxf(m, s_max[t][w]);

        const bool diag = (j == i0 + t);
        // prefilter: e <= 4.5e-5*m provably implies 2l <= -20 (certain 0);
        // survivors run the exact div+logf+test -> decisions bit-identical.
        if (diag || ed[t] > __fmul_rn(4.5e-5f, m)) {
            float p;
            if (diag) p = 0.99f;                              // (0 + 1)*0.99
            else      p = __fmul_rn(__fdiv_rn(ed[t], m), 0.99f);
            float l = logf(__fdiv_rn(p, __fsub_rn(1.0f, p)));
            if (!(__fadd_rn(l, l) <= -20.0f)) {               // uncertain
                uint32_t r = atomicAdd(&s_cnt, 1u);
                s_key[r] = ((uint32_t)b << 18) | ((uint32_t)(i0 + t) << 9) | (uint32_t)j;
                s_lg [r] = l;
            }
        }
    }
    __syncthreads();

    const uint32_t n = s_cnt;
    for (uint32_t k = threadIdx.x; k < n; k += KQ) {
        uint32_t key = s_key[k];
        float l = s_lg[k];
        uint32_t flat = key << 1;      // flat index into (B,K,K,2)
        float g0 = gumbel_from_bits(jax_bits_partitionable(flat));
        float g1 = gumbel_from_bits(jax_bits_partitionable(flat + 1u));
        // argmax over {l+g0, -l+g1}; tie -> index 0 -> sample = 1
        if (__fadd_rn(l, g0) >= __fadd_rn(-l, g1))
            atomicAdd(out + (key & 0x3FFFFu), 0.125f);   // exact multiples of 1/8
    }
}

// ---------------------------------------------------------------------------
extern "C" void kernel_launch(void* const* d_in, const int* in_sizes, int n_in,
                              void* d_out, int out_size) {
    const float* amp = (const float*)d_in[0];   // (B, C, K)
    const float* ph  = (const float*)d_in[1];   // (B, C, K)
    const float* A   = (const float*)d_in[2];   // (K, K)
    const float* wa  = (const float*)d_in[3];   // scalar
    const float* wp  = (const float*)d_in[4];   // scalar
    float* out = (float*)d_out;                  // (K, K)

    cudaMemsetAsync(out, 0, KQ * KQ * sizeof(float));
    dim3 gA(NPAIR_T, BQ);
    k_dist<<<gA, 256>>>(amp, ph, A, wa, wp);
    dim3 gB(KQ / ITB, BQ);
    k_samp<<<gB, KQ>>>(out);
}

// round 14
// speedup vs baseline: 1.6039x; 1.0011x over previous
#include <cuda_runtime.h>
#include <cstdint>

#define BQ 8
#define CQ 32
#define KQ 512
#define TI 64                       // tile side for k_dist
#define NT (KQ / TI)                // 8 tiles per side
#define NPAIR_T (NT * (NT + 1) / 2) // 36 triangular tile pairs
#define ITB 4                       // i-rows per block in k_samp
#define MAXL (ITB * KQ)

// dist scratch (B, K, K) fp32 = 8MB; per-row off-diag min (uint-cast floats)
__device__ float    g_dist[BQ * KQ * KQ];
__device__ uint32_t g_rmin[BQ * KQ];

// ---------------------------------------------------------------------------
// Threefry-2x32, key (0, 42); partitionable: bits(idx) = o0 ^ o1.
// ---------------------------------------------------------------------------
__device__ __forceinline__ uint32_t rotl32(uint32_t x, int r) {
    return (x << r) | (x >> (32 - r));
}
__device__ __forceinline__ void threefry_0_42(uint32_t x0, uint32_t x1,
                                              uint32_t& o0, uint32_t& o1) {
    const uint32_t ks0 = 0u, ks1 = 42u, ks2 = 0u ^ 42u ^ 0x1BD11BDAu;
    x0 += ks0; x1 += ks1;
    x0 += x1; x1 = rotl32(x1, 13); x1 ^= x0;
    x0 += x1; x1 = rotl32(x1, 15); x1 ^= x0;
    x0 += x1; x1 = rotl32(x1, 26); x1 ^= x0;
    x0 += x1; x1 = rotl32(x1, 6);  x1 ^= x0;
    x0 += ks1; x1 += ks2 + 1u;
    x0 += x1; x1 = rotl32(x1, 17); x1 ^= x0;
    x0 += x1; x1 = rotl32(x1, 29); x1 ^= x0;
    x0 += x1; x1 = rotl32(x1, 16); x1 ^= x0;
    x0 += x1; x1 = rotl32(x1, 24); x1 ^= x0;
    x0 += ks2; x1 += ks0 + 2u;
    x0 += x1; x1 = rotl32(x1, 13); x1 ^= x0;
    x0 += x1; x1 = rotl32(x1, 15); x1 ^= x0;
    x0 += x1; x1 = rotl32(x1, 26); x1 ^= x0;
    x0 += x1; x1 = rotl32(x1, 6);  x1 ^= x0;
    x0 += ks0; x1 += ks1 + 3u;
    x0 += x1; x1 = rotl32(x1, 17); x1 ^= x0;
    x0 += x1; x1 = rotl32(x1, 29); x1 ^= x0;
    x0 += x1; x1 = rotl32(x1, 16); x1 ^= x0;
    x0 += x1; x1 = rotl32(x1, 24); x1 ^= x0;
    x0 += ks1; x1 += ks2 + 4u;
    x0 += x1; x1 = rotl32(x1, 13); x1 ^= x0;
    x0 += x1; x1 = rotl32(x1, 15); x1 ^= x0;
    x0 += x1; x1 = rotl32(x1, 26); x1 ^= x0;
    x0 += x1; x1 = rotl32(x1, 6);  x1 ^= x0;
    x0 += ks2; x1 += ks0 + 5u;
    o0 = x0; o1 = x1;
}
__device__ __forceinline__ uint32_t jax_bits_partitionable(uint32_t idx) {
    uint32_t o0, o1;
    threefry_0_42(0u, idx, o0, o1);
    return o0 ^ o1;
}
__device__ __forceinline__ float gumbel_from_bits(uint32_t bits) {
    float f = __uint_as_float((bits >> 9) | 0x3F800000u) - 1.0f;
    float u = fmaxf(__fadd_rn(f, 1e-10f), 1e-10f);
    return -logf(-logf(u));
}

// ---------------------------------------------------------------------------
// Kernel A: symmetric pairwise distance tiles + per-row off-diag min.
// grid (NPAIR_T, BQ) = (36, 8), 256 threads; thread owns a 4x4 pair subtile.
// ---------------------------------------------------------------------------
__global__ void __launch_bounds__(256)
k_dist(const float* __restrict__ amp, const float* __restrict__ ph,
       const float* __restrict__ A,
       const float* __restrict__ wa_p, const float* __restrict__ wp_p) {
    const int b = blockIdx.y;
    int x = blockIdx.x, ti = 0;
    while (x >= NT - ti) { x -= NT - ti; ti++; }   // triangular map, ti<=tj
    const int tj = ti + x;
    const int i0 = ti * TI, j0 = tj * TI;
    const int tid = threadIdx.x;
    const int si = (tid >> 4) << 2;    // sub-row base   0..60
    const int sj = (tid & 15) << 2;    // sub-col base   0..60

    __shared__ float sAi[CQ][TI], sPi[CQ][TI];
    __shared__ float sAj[CQ][TI], sPj[CQ][TI];
    __shared__ float sDi[TI], sDj[TI];       // column-diag factors
    __shared__ uint32_t sMinI[TI], sMinJ[TI];

    const float wa = wa_p[0];
    const float wp = wp_p[0];
    // wa = wp = 0.5 fast path is bit-exact: rn(0.5*x) exact, so
    // rn(f*Ajj) = rn(s*(0.5*Ajj)) with s = rn(ad+pd).
    const bool half = (__float_as_uint(wa) == 0x3F000000u) &&
                      (__float_as_uint(wp) == 0x3F000000u);

    for (int f4 = tid; f4 < CQ * (TI / 4); f4 += 256) {   // 512 float4s/array
        int c  = f4 >> 4;
        int t4 = (f4 & 15) << 2;
        const float* ab = amp + (size_t)(b * CQ + c) * KQ;
        const float* pb = ph  + (size_t)(b * CQ + c) * KQ;
        *(float4*)&sAi[c][t4] = *(const float4*)&ab[i0 + t4];
        *(float4*)&sPi[c][t4] = *(const float4*)&pb[i0 + t4];
        *(float4*)&sAj[c][t4] = *(const float4*)&ab[j0 + t4];
        *(float4*)&sPj[c][t4] = *(const float4*)&pb[j0 + t4];
    }
    if (tid < TI) {
        float di = A[(size_t)(i0 + tid) * KQ + i0 + tid];
        float dj = A[(size_t)(j0 + tid) * KQ + j0 + tid];
        sDi[tid] = half ? __fmul_rn(0.5f, di) : di;   // exact halving
        sDj[tid] = half ? __fmul_rn(0.5f, dj) : dj;
        sMinI[tid] = 0x7F7FFFFFu;   // +FLT_MAX
        sMinJ[tid] = 0x7F7FFFFFu;
    }
    __syncthreads();

    float dI[4], dJ[4];
#pragma unroll
    for (int u = 0; u < 4; u++) { dI[u] = sDi[si + u]; dJ[u] = sDj[sj + u]; }

    float accIJ[4][4], accJI[4][4];
#pragma unroll
    for (int u = 0; u < 4; u++)
#pragma unroll
        for (int v = 0; v < 4; v++) { accIJ[u][v] = 0.0f; accJI[u][v] = 0.0f; }

    if (ti != tj) {
        // ---- off-diagonal tile pair: symmetric 9-op/2-elem chain ----
        if (half) {
#pragma unroll 4
            for (int c = 0; c < CQ; c++) {
                float4 ai = *(const float4*)&sAi[c][si];
                float4 pi = *(const float4*)&sPi[c][si];
                float4 aj = *(const float4*)&sAj[c][sj];
                float4 pj = *(const float4*)&sPj[c][sj];
                float AI[4] = {ai.x, ai.y, ai.z, ai.w};
                float PI[4] = {pi.x, pi.y, pi.z, pi.w};
                float AJ[4] = {aj.x, aj.y, aj.z, aj.w};
                float PJ[4] = {pj.x, pj.y, pj.z, pj.w};
#pragma unroll
                for (int u = 0; u < 4; u++)
#pragma unroll
                    for (int v = 0; v < 4; v++) {
                        float ad = __fsub_rn(AI[u], AJ[v]);
                        float pd = __fsub_rn(PI[u], PJ[v]);
                        float s  = __fadd_rn(ad, pd);           // = 2*f exactly
                        float u1 = __fmul_rn(s, dJ[v]);         // (i,j) col-diag j
                        accIJ[u][v] = __fadd_rn(__fmul_rn(u1, u1), accIJ[u][v]);
                        float u2 = __fmul_rn(s, dI[u]);         // (j,i) col-diag i
                        accJI[v][u] = __fadd_rn(__fmul_rn(u2, u2), accJI[v][u]);
                    }
            }
        } else {
#pragma unroll 4
            for (int c = 0; c < CQ; c++) {
                float4 ai = *(const float4*)&sAi[c][si];
                float4 pi = *(const float4*)&sPi[c][si];
                float4 aj = *(const float4*)&sAj[c][sj];
                float4 pj = *(const float4*)&sPj[c][sj];
                float AI[4] = {ai.x, ai.y, ai.z, ai.w};
                float PI[4] = {pi.x, pi.y, pi.z, pi.w};
                float AJ[4] = {aj.x, aj.y, aj.z, aj.w};
                float PJ[4] = {pj.x, pj.y, pj.z, pj.w};
#pragma unroll
                for (int u = 0; u < 4; u++)
#pragma unroll
                    for (int v = 0; v < 4; v++) {
                        float ad = __fsub_rn(AI[u], AJ[v]);
                        float pd = __fsub_rn(PI[u], PJ[v]);
                        float f  = __fadd_rn(__fmul_rn(wa, ad), __fmul_rn(wp, pd));
                        float u1 = __fmul_rn(f, dJ[v]);
                        accIJ[u][v] = __fadd_rn(__fmul_rn(u1, u1), accIJ[u][v]);
                        float u2 = __fmul_rn(f, dI[u]);   // f_ji=-f; sign dies in square
                        accJI[v][u] = __fadd_rn(__fmul_rn(u2, u2), accJI[v][u]);
                    }
            }
        }
    } else {
        // ---- diagonal tile: direct chain, full coverage, no double work ----
        if (half) {
#pragma unroll 4
            for (int c = 0; c < CQ; c++) {
                float4 ai = *(const float4*)&sAi[c][si];
                float4 pi = *(const float4*)&sPi[c][si];
                float4 aj = *(const float4*)&sAj[c][sj];
                float4 pj = *(const float4*)&sPj[c][sj];
                float AI[4] = {ai.x, ai.y, ai.z, ai.w};
                float PI[4] = {pi.x, pi.y, pi.z, pi.w};
                float AJ[4] = {aj.x, aj.y, aj.z, aj.w};
                float PJ[4] = {pj.x, pj.y, pj.z, pj.w};
#pragma unroll
                for (int u = 0; u < 4; u++)
#pragma unroll
                    for (int v = 0; v < 4; v++) {
                        float ad = __fsub_rn(AI[u], AJ[v]);
                        float pd = __fsub_rn(PI[u], PJ[v]);
                        float s  = __fadd_rn(ad, pd);
                        float u1 = __fmul_rn(s, dJ[v]);
                        accIJ[u][v] = __fadd_rn(__fmul_rn(u1, u1), accIJ[u][v]);
                    }
            }
        } else {
#pragma unroll 4
            for (int c = 0; c < CQ; c++) {
                float4 ai = *(const float4*)&sAi[c][si];
                float4 pi = *(const float4*)&sPi[c][si];
                float4 aj = *(const float4*)&sAj[c][sj];
                float4 pj = *(const float4*)&sPj[c][sj];
                float AI[4] = {ai.x, ai.y, ai.z, ai.w};
                float PI[4] = {pi.x, pi.y, pi.z, pi.w};
                float AJ[4] = {aj.x, aj.y, aj.z, aj.w};
                float PJ[4] = {pj.x, pj.y, pj.z, pj.w};
#pragma unroll
                for (int u = 0; u < 4; u++)
#pragma unroll
                    for (int v = 0; v < 4; v++) {
                        float ad = __fsub_rn(AI[u], AJ[v]);
                        float pd = __fsub_rn(PI[u], PJ[v]);
                        float f  = __fadd_rn(__fmul_rn(wa, ad), __fmul_rn(wp, pd));
                        float u1 = __fmul_rn(f, dJ[v]);
                        accIJ[u][v] = __fadd_rn(__fmul_rn(u1, u1), accIJ[u][v]);
                    }
            }
        }
    }

    // write results + per-row off-diag mins (uint-ordered atomicMin on
    // non-negative floats is exact)
    float* gd = g_dist + (size_t)b * KQ * KQ;
#pragma unroll
    for (int u = 0; u < 4; u++) {
        float4 v4 = make_float4(accIJ[u][0], accIJ[u][1], accIJ[u][2], accIJ[u][3]);
        *(float4*)&gd[(size_t)(i0 + si + u) * KQ + j0 + sj] = v4;
        float mn = 3.4e38f;
#pragma unroll
        for (int v = 0; v < 4; v++) {
            bool isdiag = (ti == tj) && (si + u == sj + v);
            if (!isdiag) mn = fminf(mn, accIJ[u][v]);
        }
        atomicMin(&sMinI[si + u], __float_as_uint(mn));
    }
    if (ti != tj) {
#pragma unroll
        for (int v = 0; v < 4; v++) {
            float4 v4 = make_float4(accJI[v][0], accJI[v][1], accJI[v][2], accJI[v][3]);
            *(float4*)&gd[(size_t)(j0 + sj + v) * KQ + i0 + si] = v4;
            float mn = fminf(fminf(accJI[v][0], accJI[v][1]),
                             fminf(accJI[v][2], accJI[v][3]));
            atomicMin(&sMinJ[sj + v], __float_as_uint(mn));
        }
    }
    __syncthreads();
    if (tid < TI) {
        atomicMin(&g_rmin[b * KQ + i0 + tid], sMinI[tid]);
        if (ti != tj) atomicMin(&g_rmin[b * KQ + j0 + tid], sMinJ[tid]);
    }
}

// ---------------------------------------------------------------------------
// Kernel B: div-free prefilter -> block-local compaction -> dense gumbel drain.
// grid (KQ/ITB, BQ) = (128, 8), 512 threads; 128 threads per row (float4/thr).
// m = rn(1/rn(dmin+1e-10)) equals the reference row max of e (monotonicity of
// rn add/div). Prefilter d_eps < R, R = rn(1/rn(4.0e-5*m)): conservative
// superset of the proven e > 4.5e-5*m filter (12% margin >> ulp slop);
// survivors run the exact div+logf+test chain -> decisions bit-identical.
// ---------------------------------------------------------------------------
__global__ void __launch_bounds__(KQ)
k_samp(float* __restrict__ out) {
    const int b  = blockIdx.y;
    const int i0 = blockIdx.x * ITB;
    const int t    = threadIdx.x >> 7;          // row 0..3
    const int lane = threadIdx.x & 127;         // 128 threads per row
    const int j4   = lane << 2;

    __shared__ float    s_m[ITB], s_R[ITB];
    __shared__ uint32_t s_cnt;
    __shared__ uint32_t s_key[MAXL];
    __shared__ float    s_lg [MAXL];

    if (threadIdx.x == 0) s_cnt = 0;
    if (threadIdx.x < ITB) {
        float dmin = __uint_as_float(g_rmin[b * KQ + i0 + threadIdx.x]);
        float m = __fdiv_rn(1.0f, __fadd_rn(dmin, 1e-10f));  // = ref row max
        s_m[threadIdx.x] = m;
        s_R[threadIdx.x] = __fdiv_rn(1.0f, __fmul_rn(4.0e-5f, m));
    }
    __syncthreads();

    const int   i = i0 + t;
    const float m = s_m[t];
    const float R = s_R[t];
    float4 d4 = *(const float4*)&g_dist[(size_t)(b * KQ + i) * KQ + j4];
    float dv[4] = {d4.x, d4.y, d4.z, d4.w};

#pragma unroll
    for (int q = 0; q < 4; q++) {
        const int j = j4 + q;
        const bool diag = (j == i);
        float de = __fadd_rn(dv[q], 1e-10f);
        if (diag || de < R) {
            float p;
            if (diag) {
                p = 0.99f;                                   // (0 + 1)*0.99
            } else {
                float e = __fdiv_rn(1.0f, de);               // exact ref e
                p = __fmul_rn(__fdiv_rn(e, m), 0.99f);
            }
            float l = logf(__fdiv_rn(p, __fsub_rn(1.0f, p)));
            if (!(__fadd_rn(l, l) <= -20.0f)) {              // uncertain
                uint32_t r = atomicAdd(&s_cnt, 1u);
                s_key[r] = ((uint32_t)b << 18) | ((uint32_t)i << 9) | (uint32_t)j;
                s_lg [r] = l;
            }
        }
    }
    __syncthreads();

    const uint32_t n = s_cnt;
    for (uint32_t k = threadIdx.x; k < n; k += KQ) {
        uint32_t key = s_key[k];
        float l = s_lg[k];
        uint32_t flat = key << 1;      // flat index into (B,K,K,2)
        float g0 = gumbel_from_bits(jax_bits_partitionable(flat));
        float g1 = gumbel_from_bits(jax_bits_partitionable(flat + 1u));
        // argmax over {l+g0, -l+g1}; tie -> index 0 -> sample = 1
        if (__fadd_rn(l, g0) >= __fadd_rn(-l, g1))
            atomicAdd(out + (key & 0x3FFFFu), 0.125f);   // exact multiples of 1/8
    }
}

// ---------------------------------------------------------------------------
extern "C" void kernel_launch(void* const* d_in, const int* in_sizes, int n_in,
                              void* d_out, int out_size) {
    const float* amp = (const float*)d_in[0];   // (B, C, K)
    const float* ph  = (const float*)d_in[1];   // (B, C, K)
    const float* A   = (const float*)d_in[2];   // (K, K)
    const float* wa  = (const float*)d_in[3];   // scalar
    const float* wp  = (const float*)d_in[4];   // scalar
    float* out = (float*)d_out;                  // (K, K)

    void* rmin_addr = nullptr;
    cudaGetSymbolAddress(&rmin_addr, g_rmin);
    cudaMemsetAsync(rmin_addr, 0x7F, BQ * KQ * sizeof(uint32_t));  // ~+FLT_MAX
    cudaMemsetAsync(out, 0, KQ * KQ * sizeof(float));

    dim3 gA(NPAIR_T, BQ);
    k_dist<<<gA, 256>>>(amp, ph, A, wa, wp);
    dim3 gB(KQ / ITB, BQ);
    k_samp<<<gB, KQ>>>(out);
}